// round 3
// baseline (speedup 1.0000x reference)
#include <cuda_runtime.h>
#include <cuda_bf16.h>
#include <cfloat>

#define G_BOXES 50
#define INF_V 100000000.0f
#define NUM_CLASSES_F 80.0f

__global__ void __launch_bounds__(256, 4) assign_targets_kernel(
    const float* __restrict__ loc,       // [L,2]
    const float* __restrict__ stride,    // [L]
    const float* __restrict__ sr,        // [L,2]
    const float* __restrict__ boxes,     // [B,G,4]
    const int*   __restrict__ classes,   // [B,G]
    float* __restrict__ out,             // [6*B*L] = labels | reg | ctr
    int L, int B)
{
    __shared__ float4 sbox[G_BOXES];   // x1,y1,x2,y2
    __shared__ float4 saux[G_BOXES];   // cx,cy,area,cls(as float)

    const int b = blockIdx.y;
    const int t = threadIdx.x;

    if (t < G_BOXES) {
        float4 bx = ((const float4*)boxes)[b * G_BOXES + t];
        sbox[t] = bx;
        float cx = (bx.x + bx.z) * 0.5f;
        float cy = (bx.y + bx.w) * 0.5f;
        float area = (bx.z - bx.x) * (bx.w - bx.y);
        saux[t] = make_float4(cx, cy, area, (float)classes[b * G_BOXES + t]);
    }
    __syncthreads();

    // two locations per thread
    const int base = blockIdx.x * 512;
    const int i0 = base + t;
    const int i1 = base + 256 + t;
    const bool v0 = i0 < L;
    const bool v1 = i1 < L;
    const int c0 = v0 ? i0 : L - 1;
    const int c1 = v1 ? i1 : L - 1;

    const float2 xy0 = ((const float2*)loc)[c0];
    const float2 xy1 = ((const float2*)loc)[c1];
    const float2 sr0 = ((const float2*)sr)[c0];
    const float2 sr1 = ((const float2*)sr)[c1];
    const float  s0  = stride[c0];
    const float  s1  = stride[c1];
    const float  rad0 = s0 * 1.5f;
    const float  rad1 = s1 * 1.5f;

    float best0 = FLT_MAX, best1 = FLT_MAX;  // > INF_V: all-invalid -> bg stays claimed by g=0
    int   bg0 = 0, bg1 = 0;

    #pragma unroll 10
    for (int g = 0; g < G_BOXES; g++) {
        const float4 bx = sbox[g];   // LDS.128 broadcast
        const float4 ax = saux[g];   // LDS.128 broadcast
        // ---- location 0 ----
        {
            const float l  = xy0.x - bx.x;
            const float tt = xy0.y - bx.y;
            const float r  = bx.z - xy0.x;
            const float bb = bx.w - xy0.y;
            const float maxd = fmaxf(fabsf(xy0.x - ax.x), fabsf(xy0.y - ax.y));
            const float m4   = fminf(fminf(l, r), fminf(tt, bb));
            const float mr   = fminf(fmaxf(l, r), fmaxf(tt, bb));
            // (mr>=lo && mr<=hi) <=> (mr-lo)*(hi-mr) >= 0   (lo<hi, magnitudes safe)
            const float w    = (mr - sr0.x) * (sr0.y - mr);
            const bool  p    = (maxd < rad0) & (m4 > 0.0f) & (w >= 0.0f);
            const float cand = p ? ax.z : INF_V;
            // branchless argmin: 4-cycle carried chains only
            bg0   = (cand < best0) ? g : bg0;
            best0 = fminf(best0, cand);
        }
        // ---- location 1 ----
        {
            const float l  = xy1.x - bx.x;
            const float tt = xy1.y - bx.y;
            const float r  = bx.z - xy1.x;
            const float bb = bx.w - xy1.y;
            const float maxd = fmaxf(fabsf(xy1.x - ax.x), fabsf(xy1.y - ax.y));
            const float m4   = fminf(fminf(l, r), fminf(tt, bb));
            const float mr   = fminf(fmaxf(l, r), fmaxf(tt, bb));
            const float w    = (mr - sr1.x) * (sr1.y - mr);
            const bool  p    = (maxd < rad1) & (m4 > 0.0f) & (w >= 0.0f);
            const float cand = p ? ax.z : INF_V;
            bg1   = (cand < best1) ? g : bg1;
            best1 = fminf(best1, cand);
        }
    }

    const size_t BL = (size_t)B * L;

    if (v0) {
        const float4 wb = sbox[bg0];
        const float4 wa = saux[bg0];
        const float l  = (xy0.x - wb.x) / s0;
        const float tt = (xy0.y - wb.y) / s0;
        const float r  = (wb.z - xy0.x) / s0;
        const float bb = (wb.w - xy0.y) / s0;
        const float label = (best0 >= INF_V) ? NUM_CLASSES_F : wa.w;
        const float rl = l + 1e-5f, rr = r + 1e-5f;
        const float rt = tt + 1e-5f, rb = bb + 1e-5f;
        float ctr = (fminf(rl, rr) / fmaxf(rl, rr)) * (fminf(rt, rb) / fmaxf(rt, rb));
        ctr = sqrtf(fmaxf(ctr, 0.0f));
        const size_t idx = (size_t)b * L + i0;
        out[idx] = label;
        ((float4*)(out + BL))[idx] = make_float4(l, tt, r, bb);
        out[5 * BL + idx] = ctr;
    }
    if (v1) {
        const float4 wb = sbox[bg1];
        const float4 wa = saux[bg1];
        const float l  = (xy1.x - wb.x) / s1;
        const float tt = (xy1.y - wb.y) / s1;
        const float r  = (wb.z - xy1.x) / s1;
        const float bb = (wb.w - xy1.y) / s1;
        const float label = (best1 >= INF_V) ? NUM_CLASSES_F : wa.w;
        const float rl = l + 1e-5f, rr = r + 1e-5f;
        const float rt = tt + 1e-5f, rb = bb + 1e-5f;
        float ctr = (fminf(rl, rr) / fmaxf(rl, rr)) * (fminf(rt, rb) / fmaxf(rt, rb));
        ctr = sqrtf(fmaxf(ctr, 0.0f));
        const size_t idx = (size_t)b * L + i1;
        out[idx] = label;
        ((float4*)(out + BL))[idx] = make_float4(l, tt, r, bb);
        out[5 * BL + idx] = ctr;
    }
}

extern "C" void kernel_launch(void* const* d_in, const int* in_sizes, int n_in,
                              void* d_out, int out_size) {
    const float* loc     = (const float*)d_in[0];   // [L,2]
    const float* stride  = (const float*)d_in[1];   // [L]
    const float* sr      = (const float*)d_in[2];   // [L,2]
    const float* boxes   = (const float*)d_in[3];   // [B,G,4]
    const int*   classes = (const int*)d_in[4];     // [B,G]
    float* out = (float*)d_out;

    const int L = in_sizes[1];
    const int B = in_sizes[4] / G_BOXES;

    dim3 block(256);
    dim3 grid((L + 511) / 512, B);
    assign_targets_kernel<<<grid, block>>>(loc, stride, sr, boxes, classes, out, L, B);
}

// round 5
// speedup vs baseline: 1.0926x; 1.0926x over previous
#include <cuda_runtime.h>
#include <cuda_bf16.h>
#include <cfloat>

#define G_BOXES 50
#define INF_V 100000000.0f
#define NUM_CLASSES_F 80.0f

typedef unsigned long long u64;

__device__ __forceinline__ u64 pk2(float lo, float hi) {
    u64 r; asm("mov.b64 %0, {%1,%2};" : "=l"(r) : "f"(lo), "f"(hi)); return r;
}
__device__ __forceinline__ float2 upk2(u64 v) {
    float2 r; asm("mov.b64 {%0,%1}, %2;" : "=f"(r.x), "=f"(r.y) : "l"(v)); return r;
}
__device__ __forceinline__ u64 add2(u64 a, u64 b) {
    u64 r; asm("add.rn.f32x2 %0, %1, %2;" : "=l"(r) : "l"(a), "l"(b)); return r;
}

__global__ void __launch_bounds__(128, 8) assign_targets_kernel(
    const float* __restrict__ loc,       // [L,2]
    const float* __restrict__ stride,    // [L]
    const float* __restrict__ sr,        // [L,2]
    const float* __restrict__ boxes,     // [B,G,4]
    const int*   __restrict__ classes,   // [B,G]
    float* __restrict__ out,             // [6*B*L] = labels | reg | ctr
    int L, int B)
{
    // box data pre-duplicated into {v,v} pairs so packed adds need no lane shuffles
    __shared__ float4 sA[G_BOXES];  // {-x1,-x1,-y1,-y1}
    __shared__ float4 sB[G_BOXES];  // { x2, x2, y2, y2}
    __shared__ float4 sC[G_BOXES];  // {-cx,-cx,-cy,-cy}
    __shared__ float2 sE[G_BOXES];  // { area, cls }

    const int b = blockIdx.y;
    const int t = threadIdx.x;

    if (t < G_BOXES) {
        float4 bx = ((const float4*)boxes)[b * G_BOXES + t];
        float cx = (bx.x + bx.z) * 0.5f;
        float cy = (bx.y + bx.w) * 0.5f;
        sA[t] = make_float4(-bx.x, -bx.x, -bx.y, -bx.y);
        sB[t] = make_float4( bx.z,  bx.z,  bx.w,  bx.w);
        sC[t] = make_float4(-cx, -cx, -cy, -cy);
        sE[t] = make_float2((bx.z - bx.x) * (bx.w - bx.y),
                            (float)classes[b * G_BOXES + t]);
    }
    __syncthreads();

    const ulonglong2* pA = (const ulonglong2*)sA;
    const ulonglong2* pB = (const ulonglong2*)sB;
    const ulonglong2* pC = (const ulonglong2*)sC;

    // two locations per thread (tile = 256 per block)
    const int base = blockIdx.x * 256;
    const int i0 = base + t;
    const int i1 = base + 128 + t;
    const bool v0 = i0 < L;
    const bool v1 = i1 < L;
    const int c0 = v0 ? i0 : L - 1;
    const int c1 = v1 ? i1 : L - 1;

    const float2 xy0 = ((const float2*)loc)[c0];
    const float2 xy1 = ((const float2*)loc)[c1];
    const float2 r0  = ((const float2*)sr)[c0];
    const float2 r1  = ((const float2*)sr)[c1];
    const float  s0  = stride[c0];
    const float  s1  = stride[c1];
    const float  rad0 = s0 * 1.5f;
    const float  rad1 = s1 * 1.5f;

    const u64 xx2  = pk2( xy0.x,  xy1.x);
    const u64 yy2  = pk2( xy0.y,  xy1.y);
    const u64 nxx2 = pk2(-xy0.x, -xy1.x);
    const u64 nyy2 = pk2(-xy0.y, -xy1.y);

    float best0 = FLT_MAX, best1 = FLT_MAX;  // > INF_V: first-occurrence argmin
    int   bg0 = 0, bg1 = 0;

    #pragma unroll 10
    for (int g = 0; g < G_BOXES; g++) {
        const ulonglong2 va = pA[g];   // LDS.128: {-x1 pair, -y1 pair}
        const ulonglong2 vb = pB[g];   // { x2 pair,  y2 pair}
        const ulonglong2 vc = pC[g];   // {-cx pair, -cy pair}
        const float2 ea = sE[g];       // LDS.64: {area, cls}

        const float2 l  = upk2(add2(xx2, va.x));   // x - x1
        const float2 tt = upk2(add2(yy2, va.y));   // y - y1
        const float2 rr = upk2(add2(vb.x, nxx2));  // x2 - x
        const float2 bb = upk2(add2(vb.y, nyy2));  // y2 - y
        const float2 dx = upk2(add2(xx2, vc.x));   // x - cx
        const float2 dy = upk2(add2(yy2, vc.y));   // y - cy

        // ---- location 0 ----
        {
            const float maxd = fmaxf(fabsf(dx.x), fabsf(dy.x));
            const float m4   = fminf(fminf(l.x, rr.x), fminf(tt.x, bb.x));
            const float mr   = fminf(fmaxf(l.x, rr.x), fmaxf(tt.x, bb.x));
            const float w    = (mr - r0.x) * (r0.y - mr);   // >=0 <=> lo<=mr<=hi
            const bool  p    = (m4 > 0.0f) & (maxd < rad0) & (w >= 0.0f);
            const float cand = p ? ea.x : INF_V;
            if (cand < best0) { best0 = cand; bg0 = g; }
        }
        // ---- location 1 ----
        {
            const float maxd = fmaxf(fabsf(dx.y), fabsf(dy.y));
            const float m4   = fminf(fminf(l.y, rr.y), fminf(tt.y, bb.y));
            const float mr   = fminf(fmaxf(l.y, rr.y), fmaxf(tt.y, bb.y));
            const float w    = (mr - r1.x) * (r1.y - mr);
            const bool  p    = (m4 > 0.0f) & (maxd < rad1) & (w >= 0.0f);
            const float cand = p ? ea.x : INF_V;
            if (cand < best1) { best1 = cand; bg1 = g; }
        }
    }

    const size_t BL = (size_t)B * L;

    if (v0) {
        const float4 wa = sA[bg0];   // {-x1,-x1,-y1,-y1}
        const float4 wb = sB[bg0];   // { x2, x2, y2, y2}
        const float l  = (xy0.x + wa.x) / s0;
        const float tt = (xy0.y + wa.z) / s0;
        const float r  = (wb.x - xy0.x) / s0;
        const float bb = (wb.z - xy0.y) / s0;
        const float label = (best0 >= INF_V) ? NUM_CLASSES_F : sE[bg0].y;
        const float rl = l + 1e-5f, rr = r + 1e-5f;
        const float rt = tt + 1e-5f, rb = bb + 1e-5f;
        float ctr = (fminf(rl, rr) / fmaxf(rl, rr)) * (fminf(rt, rb) / fmaxf(rt, rb));
        ctr = sqrtf(fmaxf(ctr, 0.0f));
        const size_t idx = (size_t)b * L + i0;
        out[idx] = label;
        ((float4*)(out + BL))[idx] = make_float4(l, tt, r, bb);
        out[5 * BL + idx] = ctr;
    }
    if (v1) {
        const float4 wa = sA[bg1];
        const float4 wb = sB[bg1];
        const float l  = (xy1.x + wa.x) / s1;
        const float tt = (xy1.y + wa.z) / s1;
        const float r  = (wb.x - xy1.x) / s1;
        const float bb = (wb.z - xy1.y) / s1;
        const float label = (best1 >= INF_V) ? NUM_CLASSES_F : sE[bg1].y;
        const float rl = l + 1e-5f, rr = r + 1e-5f;
        const float rt = tt + 1e-5f, rb = bb + 1e-5f;
        float ctr = (fminf(rl, rr) / fmaxf(rl, rr)) * (fminf(rt, rb) / fmaxf(rt, rb));
        ctr = sqrtf(fmaxf(ctr, 0.0f));
        const size_t idx = (size_t)b * L + i1;
        out[idx] = label;
        ((float4*)(out + BL))[idx] = make_float4(l, tt, r, bb);
        out[5 * BL + idx] = ctr;
    }
}

extern "C" void kernel_launch(void* const* d_in, const int* in_sizes, int n_in,
                              void* d_out, int out_size) {
    const float* loc     = (const float*)d_in[0];   // [L,2]
    const float* stride  = (const float*)d_in[1];   // [L]
    const float* sr      = (const float*)d_in[2];   // [L,2]
    const float* boxes   = (const float*)d_in[3];   // [B,G,4]
    const int*   classes = (const int*)d_in[4];     // [B,G]
    float* out = (float*)d_out;

    const int L = in_sizes[1];
    const int B = in_sizes[4] / G_BOXES;

    dim3 block(128);
    dim3 grid((L + 255) / 256, B);
    assign_targets_kernel<<<grid, block>>>(loc, stride, sr, boxes, classes, out, L, B);
}